// round 3
// baseline (speedup 1.0000x reference)
#include <cuda_runtime.h>
#include <cstdint>

#define N_NODES 50000
#define N_EDGES 800000
#define F_IN 512
#define H1 64
#define H2 128
#define N_CLASSES 10
#define N_GRAPHS 64

// ---------------- scratch (device globals; no allocation) ----------------
constexpr int OFF_AGG1 = 0;                          // N*H1
constexpr int OFF_AGG2 = OFF_AGG1 + N_NODES * H1;    // N*H2
constexpr int OFF_DEG  = OFF_AGG2 + N_NODES * H2;    // N
constexpr int OFF_POOL = OFF_DEG + N_NODES;          // G*H2
constexpr int OFF_CNT  = OFF_POOL + N_GRAPHS * H2;   // G
constexpr int ZTOTAL   = OFF_CNT + N_GRAPHS;

static_assert(ZTOTAL % 4 == 0, "zero region must be float4-able");

__device__ __align__(16) float g_z[ZTOTAL];
__device__ __align__(16) float g_ar1[N_NODES * 128];   // [N,0:64]=x@w1_l, [N,64:128]=x@w1_r
__device__ __align__(16) float g_h1[N_NODES * H1];
__device__ __align__(16) float g_ar2[N_NODES * 256];   // [N,0:128]=h1@w2_l, [N,128:256]=h1@w2_r
__device__ __align__(16) float g_w1[F_IN * 128];
__device__ __align__(16) float g_w2[H1 * 256];
__device__ int g_is64;

// ---------------- helpers ----------------
__device__ __forceinline__ void red_add_v4(float* addr, float4 v) {
    asm volatile("red.global.add.v4.f32 [%0], {%1,%2,%3,%4};"
                 :: "l"(__cvta_generic_to_global(addr)),
                    "f"(v.x), "f"(v.y), "f"(v.z), "f"(v.w)
                 : "memory");
}

__device__ __forceinline__ int load_idx(const void* p, int i, int is64) {
    if (is64) return (int)((const long long*)p)[i];
    return ((const int*)p)[i];
}

// ---------------- kernels ----------------
// Dtype probe: batch is sorted int in [0, 64). Viewed as int32 words, word
// N_NODES-1 (odd index) is 0 iff the underlying data is little-endian int64
// (it's the high half of batch[(N-1)/2]); if data is int32, it's batch[N-1]=63.
__global__ void k_detect(const void* batch_raw) {
    const int* w = (const int*)batch_raw;
    g_is64 = (w[N_NODES - 1] == 0) ? 1 : 0;
}

__global__ void k_zero() {
    int i = blockIdx.x * blockDim.x + threadIdx.x;
    if (i < ZTOTAL / 4)
        reinterpret_cast<float4*>(g_z)[i] = make_float4(0.f, 0.f, 0.f, 0.f);
}

__global__ void k_pack(const float* __restrict__ w1l, const float* __restrict__ w1r,
                       const float* __restrict__ w2l, const float* __restrict__ w2r) {
    int idx = blockIdx.x * blockDim.x + threadIdx.x;
    const int N1 = F_IN * 128;
    const int N2 = H1 * 256;
    if (idx < N1) {
        int k = idx >> 7, j = idx & 127;
        g_w1[idx] = (j < 64) ? w1l[k * 64 + j] : w1r[k * 64 + (j - 64)];
    } else if (idx < N1 + N2) {
        int t = idx - N1;
        int k = t >> 8, j = t & 255;
        g_w2[t] = (j < 128) ? w2l[k * 128 + j] : w2r[k * 128 + (j - 128)];
    }
}

__global__ void k_deg(const void* __restrict__ ei) {
    int e = blockIdx.x * blockDim.x + threadIdx.x;
    int is64 = g_is64;
    if (e < N_EDGES) {
        int d = load_idx(ei, N_EDGES + e, is64);
        atomicAdd(&g_z[OFF_DEG + d], 1.0f);
    }
}

__global__ void k_cnt(const void* __restrict__ batch) {
    int i = blockIdx.x * blockDim.x + threadIdx.x;
    int is64 = g_is64;
    if (i < N_NODES) {
        int g = load_idx(batch, i, is64);
        atomicAdd(&g_z[OFF_CNT + g], 1.0f);
    }
}

// Generic tiled GEMM: out[N,C] = X[N,K] @ W[K,C].  256 threads, 8x4 reg tile.
template <int K, int C>
__device__ __forceinline__ void gemm_body(const float* __restrict__ X,
                                          const float* __restrict__ W,
                                          float* __restrict__ out, int n) {
    constexpr int TX = C / 4;
    constexpr int TY = 256 / TX;
    constexpr int BM = TY * 8;
    constexpr int KC = 32;

    __shared__ __align__(16) float xs[KC][BM + 4];
    __shared__ __align__(16) float wb[KC][C];

    int tid = threadIdx.x;
    int tx = tid % TX, ty = tid / TX;
    int col0 = tx * 4, r0 = ty * 8;
    int rb = blockIdx.x * BM;

    float acc[8][4];
#pragma unroll
    for (int r = 0; r < 8; r++)
#pragma unroll
        for (int c = 0; c < 4; c++) acc[r][c] = 0.f;

    for (int kc = 0; kc < K; kc += KC) {
        for (int i = tid; i < KC * BM; i += 256) {
            int r = i / KC, k = i % KC;
            int gr = rb + r;
            xs[k][r] = (gr < n) ? X[gr * K + kc + k] : 0.f;
        }
        for (int i = tid; i < KC * C; i += 256) {
            int k = i / C, c = i % C;
            wb[k][c] = W[(kc + k) * C + c];
        }
        __syncthreads();
#pragma unroll
        for (int k = 0; k < KC; k++) {
            float4 b4 = *reinterpret_cast<const float4*>(&wb[k][col0]);
            float4 a0 = *reinterpret_cast<const float4*>(&xs[k][r0]);
            float4 a1 = *reinterpret_cast<const float4*>(&xs[k][r0 + 4]);
            float a[8] = {a0.x, a0.y, a0.z, a0.w, a1.x, a1.y, a1.z, a1.w};
#pragma unroll
            for (int r = 0; r < 8; r++) {
                acc[r][0] += a[r] * b4.x;
                acc[r][1] += a[r] * b4.y;
                acc[r][2] += a[r] * b4.z;
                acc[r][3] += a[r] * b4.w;
            }
        }
        __syncthreads();
    }
#pragma unroll
    for (int r = 0; r < 8; r++) {
        int gr = rb + r0 + r;
        if (gr < n)
            *reinterpret_cast<float4*>(&out[gr * C + col0]) =
                make_float4(acc[r][0], acc[r][1], acc[r][2], acc[r][3]);
    }
}

__global__ void k_gemm1(const float* __restrict__ x, int n) {
    gemm_body<F_IN, 128>(x, g_w1, g_ar1, n);
}
__global__ void k_gemm2(int n) {
    gemm_body<H1, 256>(g_h1, g_w2, g_ar2, n);
}

// scatter layer 1: agg1[dst, 0:64] += ar1[src, 0:64]
__global__ void k_scatter1(const void* __restrict__ ei) {
    int idx = blockIdx.x * blockDim.x + threadIdx.x;
    if (idx >= N_EDGES * 16) return;
    int is64 = g_is64;
    int e = idx >> 4, q = idx & 15;
    int s = load_idx(ei, e, is64);
    int d = load_idx(ei, N_EDGES + e, is64);
    float4 v = *reinterpret_cast<const float4*>(&g_ar1[s * 128 + q * 4]);
    red_add_v4(&g_z[OFF_AGG1 + d * 64 + q * 4], v);
}

__global__ void k_combine1(const float* __restrict__ b1l) {
    int idx = blockIdx.x * blockDim.x + threadIdx.x;
    if (idx >= N_NODES * H1) return;
    int i = idx >> 6, j = idx & 63;
    float inv = 1.0f / fmaxf(g_z[OFF_DEG + i], 1.0f);
    float v = g_z[OFF_AGG1 + idx] * inv + b1l[j] + g_ar1[i * 128 + 64 + j];
    g_h1[idx] = fmaxf(v, 0.0f);
}

// scatter layer 2: agg2[dst, 0:128] += ar2[src, 0:128]
__global__ void k_scatter2(const void* __restrict__ ei) {
    int idx = blockIdx.x * blockDim.x + threadIdx.x;
    if (idx >= N_EDGES * 32) return;
    int is64 = g_is64;
    int e = idx >> 5, q = idx & 31;
    int s = load_idx(ei, e, is64);
    int d = load_idx(ei, N_EDGES + e, is64);
    float4 v = *reinterpret_cast<const float4*>(&g_ar2[s * 256 + q * 4]);
    red_add_v4(&g_z[OFF_AGG2 + d * 128 + q * 4], v);
}

// combine layer-2 + fused graph-mean pooling (batch is sorted -> block-local
// register accumulation per column, flush on graph boundary only)
__global__ void k_combine2_pool(const float* __restrict__ b2l,
                                const void* __restrict__ batch, int n) {
    int node0 = blockIdx.x * 64;
    int tid = threadIdx.x;  // column 0..127
    if (node0 >= n) return;
    int is64 = g_is64;
    float bj = b2l[tid];
    float acc = 0.f;
    int curg = load_idx(batch, node0, is64);
    for (int nd = 0; nd < 64; nd++) {
        int node = node0 + nd;
        if (node >= n) break;
        int g = load_idx(batch, node, is64);
        float inv = 1.0f / fmaxf(g_z[OFF_DEG + node], 1.0f);
        float v = g_z[OFF_AGG2 + node * 128 + tid] * inv + bj +
                  g_ar2[node * 256 + 128 + tid];
        if (g != curg) {
            atomicAdd(&g_z[OFF_POOL + curg * 128 + tid], acc);
            acc = 0.f;
            curg = g;
        }
        acc += v;
    }
    atomicAdd(&g_z[OFF_POOL + curg * 128 + tid], acc);
}

__global__ void k_final(const float* __restrict__ wfc, const float* __restrict__ bfc,
                        float* __restrict__ out) {
    int g = threadIdx.x;
    if (g >= N_GRAPHS) return;
    float inv = 1.0f / fmaxf(g_z[OFF_CNT + g], 1.0f);
    float l[N_CLASSES];
#pragma unroll
    for (int c = 0; c < N_CLASSES; c++) l[c] = bfc[c];
    for (int k = 0; k < H2; k++) {
        float p = g_z[OFF_POOL + g * 128 + k] * inv;
#pragma unroll
        for (int c = 0; c < N_CLASSES; c++) l[c] += p * wfc[k * N_CLASSES + c];
    }
    float mx = l[0];
#pragma unroll
    for (int c = 1; c < N_CLASSES; c++) mx = fmaxf(mx, l[c]);
    float s = 0.f;
#pragma unroll
    for (int c = 0; c < N_CLASSES; c++) s += expf(l[c] - mx);
    float lse = mx + logf(s);
#pragma unroll
    for (int c = 0; c < N_CLASSES; c++) out[g * N_CLASSES + c] = l[c] - lse;
}

// ---------------- launch ----------------
extern "C" void kernel_launch(void* const* d_in, const int* in_sizes, int n_in,
                              void* d_out, int out_size) {
    const float* x     = (const float*)d_in[0];
    const void*  ei    = d_in[1];
    const void*  batch = d_in[2];
    const float* w1l   = (const float*)d_in[3];
    const float* b1l   = (const float*)d_in[4];
    const float* w1r   = (const float*)d_in[5];
    const float* w2l   = (const float*)d_in[6];
    const float* b2l   = (const float*)d_in[7];
    const float* w2r   = (const float*)d_in[8];
    const float* wfc   = (const float*)d_in[9];
    const float* bfc   = (const float*)d_in[10];
    float* out = (float*)d_out;

    const int n = N_NODES;

    k_detect<<<1, 1>>>(batch);
    k_zero<<<(ZTOTAL / 4 + 255) / 256, 256>>>();
    k_pack<<<(F_IN * 128 + H1 * 256 + 255) / 256, 256>>>(w1l, w1r, w2l, w2r);
    k_deg<<<(N_EDGES + 255) / 256, 256>>>(ei);
    k_cnt<<<(N_NODES + 255) / 256, 256>>>(batch);

    k_gemm1<<<(n + 63) / 64, 256>>>(x, n);
    k_scatter1<<<(N_EDGES * 16 + 255) / 256, 256>>>(ei);
    k_combine1<<<(n * H1 + 255) / 256, 256>>>(b1l);

    k_gemm2<<<(n + 31) / 32, 256>>>(n);
    k_scatter2<<<(N_EDGES * 32 + 255) / 256, 256>>>(ei);
    k_combine2_pool<<<(n + 63) / 64, 128>>>(b2l, batch, n);

    k_final<<<1, 64>>>(wfc, bfc, out);
}

// round 9
// speedup vs baseline: 1.2534x; 1.2534x over previous
#include <cuda_runtime.h>
#include <cuda_bf16.h>
#include <cstdint>

#define N_NODES 50000
#define N_EDGES 800000
#define F_IN 512
#define H1 64
#define H2 128
#define N_CLASSES 10
#define N_GRAPHS 64

// ---------------- scratch (device globals; no allocation) ----------------
constexpr int OFF_AGG1 = 0;                          // N*H1
constexpr int OFF_AGG2 = OFF_AGG1 + N_NODES * H1;    // N*H2
constexpr int OFF_DEG  = OFF_AGG2 + N_NODES * H2;    // N
constexpr int OFF_POOL = OFF_DEG + N_NODES;          // G*H2
constexpr int OFF_CNT  = OFF_POOL + N_GRAPHS * H2;   // G
constexpr int ZTOTAL   = OFF_CNT + N_GRAPHS;

static_assert(ZTOTAL % 4 == 0, "zero region must be float4-able");

__device__ __align__(16) float g_z[ZTOTAL];
__device__ __align__(16) float g_ar1[N_NODES * 128];   // [N,0:64]=x@w1_l, [N,64:128]=x@w1_r
__device__ __align__(16) float g_h1[N_NODES * H1];
__device__ __align__(16) float g_ar2[N_NODES * 256];   // [N,0:128]=h1@w2_l, [N,128:256]=h1@w2_r
// weights, bf16 hi/lo split, packed [chunk][n][k32] (k contiguous)
__device__ __align__(16) __nv_bfloat16 g_w1hb[F_IN * 128];
__device__ __align__(16) __nv_bfloat16 g_w1lb[F_IN * 128];
__device__ __align__(16) __nv_bfloat16 g_w2hb[H1 * 256];
__device__ __align__(16) __nv_bfloat16 g_w2lb[H1 * 256];
__device__ int g_is64;

// ---------------- helpers ----------------
__device__ __forceinline__ void red_add_v4(float* addr, float4 v) {
    asm volatile("red.global.add.v4.f32 [%0], {%1,%2,%3,%4};"
                 :: "l"(__cvta_generic_to_global(addr)),
                    "f"(v.x), "f"(v.y), "f"(v.z), "f"(v.w)
                 : "memory");
}

__device__ __forceinline__ int load_idx(const void* p, int i, int is64) {
    if (is64) return (int)((const long long*)p)[i];
    return ((const int*)p)[i];
}

__device__ __forceinline__ void bf16_split(float x, __nv_bfloat16& h, __nv_bfloat16& l) {
    h = __float2bfloat16_rn(x);
    l = __float2bfloat16_rn(x - __bfloat162float(h));
}

__device__ __forceinline__ void mma_bf16(float* c, const uint32_t* a, const uint32_t* b) {
    asm volatile(
        "mma.sync.aligned.m16n8k16.row.col.f32.bf16.bf16.f32 "
        "{%0,%1,%2,%3}, {%4,%5,%6,%7}, {%8,%9}, {%0,%1,%2,%3};"
        : "+f"(c[0]), "+f"(c[1]), "+f"(c[2]), "+f"(c[3])
        : "r"(a[0]), "r"(a[1]), "r"(a[2]), "r"(a[3]), "r"(b[0]), "r"(b[1]));
}

// ---------------- small kernels ----------------
__global__ void k_detect(const void* batch_raw) {
    const int* w = (const int*)batch_raw;
    g_is64 = (w[N_NODES - 1] == 0) ? 1 : 0;
}

__global__ void k_zero() {
    int i = blockIdx.x * blockDim.x + threadIdx.x;
    if (i < ZTOTAL / 4)
        reinterpret_cast<float4*>(g_z)[i] = make_float4(0.f, 0.f, 0.f, 0.f);
}

// Pack weights: bf16 hi/lo split, layout [chunk][n][kk] (kk = k % 32 contiguous).
// w1 -> n (0..127): n<64 = w1l col n, else w1r col n-64.
// w2 -> n (0..255): n<128 = w2l col n, else w2r col n-128.
__global__ void k_pack(const float* __restrict__ w1l, const float* __restrict__ w1r,
                       const float* __restrict__ w2l, const float* __restrict__ w2r) {
    int idx = blockIdx.x * blockDim.x + threadIdx.x;
    const int N1 = F_IN * 128;
    const int N2 = H1 * 256;
    if (idx < N1) {
        int k = idx >> 7, n = idx & 127;
        float v = (n < 64) ? w1l[k * 64 + n] : w1r[k * 64 + (n - 64)];
        __nv_bfloat16 h, l;
        bf16_split(v, h, l);
        int chunk = k >> 5, kk = k & 31;
        int off = (chunk * 128 + n) * 32 + kk;
        g_w1hb[off] = h;
        g_w1lb[off] = l;
    } else if (idx < N1 + N2) {
        int t = idx - N1;
        int k = t >> 8, n = t & 255;
        float v = (n < 128) ? w2l[k * 128 + n] : w2r[k * 128 + (n - 128)];
        __nv_bfloat16 h, l;
        bf16_split(v, h, l);
        int chunk = k >> 5, kk = k & 31;
        int off = (chunk * 256 + n) * 32 + kk;
        g_w2hb[off] = h;
        g_w2lb[off] = l;
    }
}

__global__ void k_deg(const void* __restrict__ ei) {
    int e = blockIdx.x * blockDim.x + threadIdx.x;
    int is64 = g_is64;
    if (e < N_EDGES) {
        int d = load_idx(ei, N_EDGES + e, is64);
        atomicAdd(&g_z[OFF_DEG + d], 1.0f);
    }
}

__global__ void k_cnt(const void* __restrict__ batch) {
    int i = blockIdx.x * blockDim.x + threadIdx.x;
    int is64 = g_is64;
    if (i < N_NODES) {
        int g = load_idx(batch, i, is64);
        atomicAdd(&g_z[OFF_CNT + g], 1.0f);
    }
}

// ---------------- mma.sync bf16x2 GEMM ----------------
// out[n, NTOT] = X[n, KTOT] @ W[KTOT, NTOT], near-fp32 via bf16 split
// (3 passes: h*H + h*L + l*H, fp32 accumulate).
// Block tile 128M x 128N, 8 warps (4M x 2N), warp tile 32M x 64N.
// gridDim.y covers NTOT/128.
// LAYER 0: X = Xin (x), W = g_w1*, out = g_ar1.
// LAYER 1: X = g_h1,    W = g_w2*, out = g_ar2.
template <int KTOT, int NTOT, int LAYER>
__global__ void __launch_bounds__(256)
k_hmma(const float* __restrict__ Xin, int n) {
    constexpr int CH = KTOT / 32;
    constexpr int PAD = 40;  // bf16 row stride: 80B, conflict-free + 16B-alignable

    __shared__ __nv_bfloat16 sAh[128][PAD];
    __shared__ __nv_bfloat16 sAl[128][PAD];
    __shared__ __nv_bfloat16 sBh[128][PAD];
    __shared__ __nv_bfloat16 sBl[128][PAD];

    const float* X = (LAYER == 0) ? Xin : (const float*)g_h1;
    const __nv_bfloat16* BH = (LAYER == 0) ? g_w1hb : g_w2hb;
    const __nv_bfloat16* BL = (LAYER == 0) ? g_w1lb : g_w2lb;
    float* out = (LAYER == 0) ? (float*)g_ar1 : (float*)g_ar2;

    int tid = threadIdx.x, wid = tid >> 5, lid = tid & 31;
    int wm = wid & 3, wn = wid >> 2;          // warp position: 4M x 2N
    int g = lid >> 2, tig = lid & 3;          // mma fragment coords
    int row0 = blockIdx.x * 128;
    int bn0 = blockIdx.y * 128;

    float acc[2][8][4];
#pragma unroll
    for (int mt = 0; mt < 2; mt++)
#pragma unroll
        for (int nt = 0; nt < 8; nt++)
#pragma unroll
            for (int q = 0; q < 4; q++) acc[mt][nt][q] = 0.f;

    for (int c = 0; c < CH; c++) {
        __syncthreads();  // previous iter's fragment reads done

        // stage A chunk: 128 rows x 32 k, fp32 -> bf16 h/l
#pragma unroll
        for (int i = 0; i < 4; i++) {
            int id = i * 256 + tid;        // 0..1023
            int r = id >> 3, q = id & 7;   // row, float4-slot
            int gr = row0 + r;
            float4 v = make_float4(0.f, 0.f, 0.f, 0.f);
            if (gr < n)
                v = *reinterpret_cast<const float4*>(
                    &X[(size_t)gr * KTOT + c * 32 + q * 4]);
            __nv_bfloat16 hx, lx, hy, ly, hz, lz, hw, lw;
            bf16_split(v.x, hx, lx);
            bf16_split(v.y, hy, ly);
            bf16_split(v.z, hz, lz);
            bf16_split(v.w, hw, lw);
            int kk = q * 4;
            *reinterpret_cast<__nv_bfloat162*>(&sAh[r][kk])     = __nv_bfloat162(hx, hy);
            *reinterpret_cast<__nv_bfloat162*>(&sAh[r][kk + 2]) = __nv_bfloat162(hz, hw);
            *reinterpret_cast<__nv_bfloat162*>(&sAl[r][kk])     = __nv_bfloat162(lx, ly);
            *reinterpret_cast<__nv_bfloat162*>(&sAl[r][kk + 2]) = __nv_bfloat162(lz, lw);
        }
        // stage B chunk: 128 rows (this block's n slice) x 32 k, pre-packed bf16
#pragma unroll
        for (int i = 0; i < 2; i++) {
            int id = i * 256 + tid;        // 0..511
            int r = id >> 2, q = id & 3;   // row, uint4-slot (8 bf16)
            const uint4* srch = reinterpret_cast<const uint4*>(
                BH + ((size_t)(c * NTOT) + bn0 + r) * 32) + q;
            const uint4* srcl = reinterpret_cast<const uint4*>(
                BL + ((size_t)(c * NTOT) + bn0 + r) * 32) + q;
            *reinterpret_cast<uint4*>(&sBh[r][q * 8]) = *srch;
            *reinterpret_cast<uint4*>(&sBl[r][q * 8]) = *srcl;
        }
        __syncthreads();

        // compute: 2 k-steps of 16
#pragma unroll
        for (int ks = 0; ks < 2; ks++) {
            int k0 = ks * 16 + 2 * tig;
            uint32_t bh[8][2], bl[8][2];
#pragma unroll
            for (int nt = 0; nt < 8; nt++) {
                int nn = wn * 64 + nt * 8 + g;
                bh[nt][0] = *reinterpret_cast<const uint32_t*>(&sBh[nn][k0]);
                bh[nt][1] = *reinterpret_cast<const uint32_t*>(&sBh[nn][k0 + 8]);
                bl[nt][0] = *reinterpret_cast<const uint32_t*>(&sBl[nn][k0]);
                bl[nt][1] = *reinterpret_cast<const uint32_t*>(&sBl[nn][k0 + 8]);
            }
#pragma unroll
            for (int mt = 0; mt < 2; mt++) {
                int r = wm * 32 + mt * 16 + g;
                uint32_t ah[4], al[4];
                ah[0] = *reinterpret_cast<const uint32_t*>(&sAh[r][k0]);
                ah[1] = *reinterpret_cast<const uint32_t*>(&sAh[r + 8][k0]);
                ah[2] = *reinterpret_cast<const uint32_t*>(&sAh[r][k0 + 8]);
                ah[3] = *reinterpret_cast<const uint32_t*>(&sAh[r + 8][k0 + 8]);
                al[0] = *reinterpret_cast<const uint32_t*>(&sAl[r][k0]);
                al[1] = *reinterpret_cast<const uint32_t*>(&sAl[r + 8][k0]);
                al[2] = *reinterpret_cast<const uint32_t*>(&sAl[r][k0 + 8]);
                al[3] = *reinterpret_cast<const uint32_t*>(&sAl[r + 8][k0 + 8]);
#pragma unroll
                for (int nt = 0; nt < 8; nt++) {
                    mma_bf16(acc[mt][nt], ah, bh[nt]);
                    mma_bf16(acc[mt][nt], ah, bl[nt]);
                    mma_bf16(acc[mt][nt], al, bh[nt]);
                }
            }
        }
    }

    // epilogue: c0,c1 -> (row rA, col cc); c2,c3 -> (row rA+8, col cc)
#pragma unroll
    for (int mt = 0; mt < 2; mt++) {
        int rA = row0 + wm * 32 + mt * 16 + g;
#pragma unroll
        for (int nt = 0; nt < 8; nt++) {
            int cc = bn0 + wn * 64 + nt * 8 + 2 * tig;
            if (rA < n)
                *reinterpret_cast<float2*>(&out[(size_t)rA * NTOT + cc]) =
                    make_float2(acc[mt][nt][0], acc[mt][nt][1]);
            if (rA + 8 < n)
                *reinterpret_cast<float2*>(&out[(size_t)(rA + 8) * NTOT + cc]) =
                    make_float2(acc[mt][nt][2], acc[mt][nt][3]);
        }
    }
}

// ---------------- scatter / combine / pool / final ----------------
__global__ void k_scatter1(const void* __restrict__ ei) {
    int idx = blockIdx.x * blockDim.x + threadIdx.x;
    if (idx >= N_EDGES * 16) return;
    int is64 = g_is64;
    int e = idx >> 4, q = idx & 15;
    int s = load_idx(ei, e, is64);
    int d = load_idx(ei, N_EDGES + e, is64);
    float4 v = *reinterpret_cast<const float4*>(&g_ar1[s * 128 + q * 4]);
    red_add_v4(&g_z[OFF_AGG1 + d * 64 + q * 4], v);
}

__global__ void k_combine1(const float* __restrict__ b1l) {
    int idx = blockIdx.x * blockDim.x + threadIdx.x;
    if (idx >= N_NODES * H1) return;
    int i = idx >> 6, j = idx & 63;
    float inv = 1.0f / fmaxf(g_z[OFF_DEG + i], 1.0f);
    float v = g_z[OFF_AGG1 + idx] * inv + b1l[j] + g_ar1[i * 128 + 64 + j];
    g_h1[idx] = fmaxf(v, 0.0f);
}

__global__ void k_scatter2(const void* __restrict__ ei) {
    int idx = blockIdx.x * blockDim.x + threadIdx.x;
    if (idx >= N_EDGES * 32) return;
    int is64 = g_is64;
    int e = idx >> 5, q = idx & 31;
    int s = load_idx(ei, e, is64);
    int d = load_idx(ei, N_EDGES + e, is64);
    float4 v = *reinterpret_cast<const float4*>(&g_ar2[s * 256 + q * 4]);
    red_add_v4(&g_z[OFF_AGG2 + d * 128 + q * 4], v);
}

__global__ void k_combine2_pool(const float* __restrict__ b2l,
                                const void* __restrict__ batch, int n) {
    int node0 = blockIdx.x * 64;
    int tid = threadIdx.x;  // column 0..127
    if (node0 >= n) return;
    int is64 = g_is64;
    float bj = b2l[tid];
    float acc = 0.f;
    int curg = load_idx(batch, node0, is64);
    for (int nd = 0; nd < 64; nd++) {
        int node = node0 + nd;
        if (node >= n) break;
        int g = load_idx(batch, node, is64);
        float inv = 1.0f / fmaxf(g_z[OFF_DEG + node], 1.0f);
        float v = g_z[OFF_AGG2 + node * 128 + tid] * inv + bj +
                  g_ar2[node * 256 + 128 + tid];
        if (g != curg) {
            atomicAdd(&g_z[OFF_POOL + curg * 128 + tid], acc);
            acc = 0.f;
            curg = g;
        }
        acc += v;
    }
    atomicAdd(&g_z[OFF_POOL + curg * 128 + tid], acc);
}

__global__ void k_final(const float* __restrict__ wfc, const float* __restrict__ bfc,
                        float* __restrict__ out) {
    int g = threadIdx.x;
    if (g >= N_GRAPHS) return;
    float inv = 1.0f / fmaxf(g_z[OFF_CNT + g], 1.0f);
    float l[N_CLASSES];
#pragma unroll
    for (int c = 0; c < N_CLASSES; c++) l[c] = bfc[c];
    for (int k = 0; k < H2; k++) {
        float p = g_z[OFF_POOL + g * 128 + k] * inv;
#pragma unroll
        for (int c = 0; c < N_CLASSES; c++) l[c] += p * wfc[k * N_CLASSES + c];
    }
    float mx = l[0];
#pragma unroll
    for (int c = 1; c < N_CLASSES; c++) mx = fmaxf(mx, l[c]);
    float s = 0.f;
#pragma unroll
    for (int c = 0; c < N_CLASSES; c++) s += expf(l[c] - mx);
    float lse = mx + logf(s);
#pragma unroll
    for (int c = 0; c < N_CLASSES; c++) out[g * N_CLASSES + c] = l[c] - lse;
}

// ---------------- launch ----------------
extern "C" void kernel_launch(void* const* d_in, const int* in_sizes, int n_in,
                              void* d_out, int out_size) {
    const float* x     = (const float*)d_in[0];
    const void*  ei    = d_in[1];
    const void*  batch = d_in[2];
    const float* w1l   = (const float*)d_in[3];
    const float* b1l   = (const float*)d_in[4];
    const float* w1r   = (const float*)d_in[5];
    const float* w2l   = (const float*)d_in[6];
    const float* b2l   = (const float*)d_in[7];
    const float* w2r   = (const float*)d_in[8];
    const float* wfc   = (const float*)d_in[9];
    const float* bfc   = (const float*)d_in[10];
    float* out = (float*)d_out;

    const int n = N_NODES;

    k_detect<<<1, 1>>>(batch);
    k_zero<<<(ZTOTAL / 4 + 255) / 256, 256>>>();
    k_pack<<<(F_IN * 128 + H1 * 256 + 255) / 256, 256>>>(w1l, w1r, w2l, w2r);
    k_deg<<<(N_EDGES + 255) / 256, 256>>>(ei);
    k_cnt<<<(N_NODES + 255) / 256, 256>>>(batch);

    dim3 grid1((n + 127) / 128, 1);
    k_hmma<512, 128, 0><<<grid1, 256>>>(x, n);
    k_scatter1<<<(N_EDGES * 16 + 255) / 256, 256>>>(ei);
    k_combine1<<<(n * H1 + 255) / 256, 256>>>(b1l);

    dim3 grid2((n + 127) / 128, 2);
    k_hmma<64, 256, 1><<<grid2, 256>>>(nullptr, n);
    k_scatter2<<<(N_EDGES * 32 + 255) / 256, 256>>>(ei);
    k_combine2_pool<<<(n + 63) / 64, 128>>>(b2l, batch, n);

    k_final<<<1, 64>>>(wfc, bfc, out);
}

// round 10
// speedup vs baseline: 1.7533x; 1.3988x over previous
#include <cuda_runtime.h>
#include <cuda_bf16.h>
#include <cstdint>

#define N_NODES 50000
#define N_EDGES 800000
#define F_IN 512
#define H1 64
#define H2 128
#define N_CLASSES 10
#define N_GRAPHS 64
#define BSTRIDE 96

// ---------------- scratch (device globals; no allocation) ----------------
__device__ __align__(16) float g_ar1[N_NODES * 128];  // [N,0:64]=x@w1_l, [N,64:128]=x@w1_r
__device__ __align__(16) float g_x2[N_NODES * 128];   // [N,0:64]=mean(h1), [N,64:128]=h1
__device__ __align__(16) float g_h2[N_NODES * 128];   // gemm2 out
__device__ __align__(16) float g_pool[N_GRAPHS * H2 + N_GRAPHS];  // pool | graph counts
__device__ int g_cnti[N_NODES];                       // in-degree / bucket cursor
__device__ int g_bucket[N_NODES * BSTRIDE];           // src lists per dst
// weights, bf16 hi/lo split, packed [chunk][n][k32] (k contiguous)
__device__ __align__(16) __nv_bfloat16 g_w1hb[F_IN * 128];
__device__ __align__(16) __nv_bfloat16 g_w1lb[F_IN * 128];
__device__ __align__(16) __nv_bfloat16 g_w2hb[128 * 128];
__device__ __align__(16) __nv_bfloat16 g_w2lb[128 * 128];
__device__ int g_is64;

// ---------------- helpers ----------------
__device__ __forceinline__ int load_idx(const void* p, int i, int is64) {
    if (is64) return (int)((const long long*)p)[i];
    return ((const int*)p)[i];
}

__device__ __forceinline__ void bf16_split(float x, __nv_bfloat16& h, __nv_bfloat16& l) {
    h = __float2bfloat16_rn(x);
    l = __float2bfloat16_rn(x - __bfloat162float(h));
}

__device__ __forceinline__ void mma_bf16(float* c, const uint32_t* a, const uint32_t* b) {
    asm volatile(
        "mma.sync.aligned.m16n8k16.row.col.f32.bf16.bf16.f32 "
        "{%0,%1,%2,%3}, {%4,%5,%6,%7}, {%8,%9}, {%0,%1,%2,%3};"
        : "+f"(c[0]), "+f"(c[1]), "+f"(c[2]), "+f"(c[3])
        : "r"(a[0]), "r"(a[1]), "r"(a[2]), "r"(a[3]), "r"(b[0]), "r"(b[1]));
}

// ---------------- small kernels ----------------
__global__ void k_detect(const void* batch_raw) {
    const int* w = (const int*)batch_raw;
    g_is64 = (w[N_NODES - 1] == 0) ? 1 : 0;
}

__global__ void k_zero() {
    int i = blockIdx.x * blockDim.x + threadIdx.x;
    if (i < N_GRAPHS * H2 + N_GRAPHS) g_pool[i] = 0.f;
    if (i < N_NODES) g_cnti[i] = 0;
}

// Pack weights bf16 hi/lo, layout [chunk][n][kk].
// W1: K=512 rows, 128 cols (0:64 = w1_l, 64:128 = w1_r).
// W2: K=128 rows (0:64 = w2_l rows applied to mean, 64:128 = w2_r rows
//     applied to h1), 128 cols.
__global__ void k_pack(const float* __restrict__ w1l, const float* __restrict__ w1r,
                       const float* __restrict__ w2l, const float* __restrict__ w2r) {
    int idx = blockIdx.x * blockDim.x + threadIdx.x;
    const int N1 = F_IN * 128;
    const int N2 = 128 * 128;
    if (idx < N1) {
        int k = idx >> 7, n = idx & 127;
        float v = (n < 64) ? w1l[k * 64 + n] : w1r[k * 64 + (n - 64)];
        __nv_bfloat16 h, l;
        bf16_split(v, h, l);
        int off = ((k >> 5) * 128 + n) * 32 + (k & 31);
        g_w1hb[off] = h;
        g_w1lb[off] = l;
    } else if (idx < N1 + N2) {
        int t = idx - N1;
        int k = t >> 7, n = t & 127;
        float v = (k < 64) ? w2l[k * 128 + n] : w2r[(k - 64) * 128 + n];
        __nv_bfloat16 h, l;
        bf16_split(v, h, l);
        int off = ((k >> 5) * 128 + n) * 32 + (k & 31);
        g_w2hb[off] = h;
        g_w2lb[off] = l;
    }
}

// bucketed CSR build: slot = cursor[dst]++, bucket[dst][slot] = src
__global__ void k_fill(const void* __restrict__ ei) {
    int e = blockIdx.x * blockDim.x + threadIdx.x;
    if (e >= N_EDGES) return;
    int is64 = g_is64;
    int s = load_idx(ei, e, is64);
    int d = load_idx(ei, N_EDGES + e, is64);
    int slot = atomicAdd(&g_cnti[d], 1);
    if (slot < BSTRIDE) g_bucket[d * BSTRIDE + slot] = s;
}

__global__ void k_cnt(const void* __restrict__ batch) {
    int i = blockIdx.x * blockDim.x + threadIdx.x;
    int is64 = g_is64;
    if (i < N_NODES) {
        int g = load_idx(batch, i, is64);
        atomicAdd(&g_pool[N_GRAPHS * H2 + g], 1.0f);
    }
}

// ---------------- mma.sync bf16x2 GEMM ----------------
// out[n, NTOT] = X[n, KTOT] @ W[KTOT, NTOT]; bf16 split, 3 passes, fp32 acc.
// Block tile 128x128, 8 warps (4M x 2N), warp tile 32x64.
template <int KTOT, int NTOT, int LAYER>
__global__ void __launch_bounds__(256)
k_hmma(const float* __restrict__ Xin, int n) {
    constexpr int CH = KTOT / 32;
    constexpr int PAD = 40;

    __shared__ __nv_bfloat16 sAh[128][PAD];
    __shared__ __nv_bfloat16 sAl[128][PAD];
    __shared__ __nv_bfloat16 sBh[128][PAD];
    __shared__ __nv_bfloat16 sBl[128][PAD];

    const float* X = (LAYER == 0) ? Xin : (const float*)g_x2;
    const __nv_bfloat16* BH = (LAYER == 0) ? g_w1hb : g_w2hb;
    const __nv_bfloat16* BL = (LAYER == 0) ? g_w1lb : g_w2lb;
    float* out = (LAYER == 0) ? (float*)g_ar1 : (float*)g_h2;

    int tid = threadIdx.x, wid = tid >> 5, lid = tid & 31;
    int wm = wid & 3, wn = wid >> 2;
    int g = lid >> 2, tig = lid & 3;
    int row0 = blockIdx.x * 128;
    int bn0 = blockIdx.y * 128;

    float acc[2][8][4];
#pragma unroll
    for (int mt = 0; mt < 2; mt++)
#pragma unroll
        for (int nt = 0; nt < 8; nt++)
#pragma unroll
            for (int q = 0; q < 4; q++) acc[mt][nt][q] = 0.f;

    for (int c = 0; c < CH; c++) {
        __syncthreads();

#pragma unroll
        for (int i = 0; i < 4; i++) {
            int id = i * 256 + tid;
            int r = id >> 3, q = id & 7;
            int gr = row0 + r;
            float4 v = make_float4(0.f, 0.f, 0.f, 0.f);
            if (gr < n)
                v = *reinterpret_cast<const float4*>(
                    &X[(size_t)gr * KTOT + c * 32 + q * 4]);
            __nv_bfloat16 hx, lx, hy, ly, hz, lz, hw, lw;
            bf16_split(v.x, hx, lx);
            bf16_split(v.y, hy, ly);
            bf16_split(v.z, hz, lz);
            bf16_split(v.w, hw, lw);
            int kk = q * 4;
            *reinterpret_cast<__nv_bfloat162*>(&sAh[r][kk])     = __nv_bfloat162(hx, hy);
            *reinterpret_cast<__nv_bfloat162*>(&sAh[r][kk + 2]) = __nv_bfloat162(hz, hw);
            *reinterpret_cast<__nv_bfloat162*>(&sAl[r][kk])     = __nv_bfloat162(lx, ly);
            *reinterpret_cast<__nv_bfloat162*>(&sAl[r][kk + 2]) = __nv_bfloat162(lz, lw);
        }
#pragma unroll
        for (int i = 0; i < 2; i++) {
            int id = i * 256 + tid;
            int r = id >> 2, q = id & 3;
            const uint4* srch = reinterpret_cast<const uint4*>(
                BH + ((size_t)(c * NTOT) + bn0 + r) * 32) + q;
            const uint4* srcl = reinterpret_cast<const uint4*>(
                BL + ((size_t)(c * NTOT) + bn0 + r) * 32) + q;
            *reinterpret_cast<uint4*>(&sBh[r][q * 8]) = *srch;
            *reinterpret_cast<uint4*>(&sBl[r][q * 8]) = *srcl;
        }
        __syncthreads();

#pragma unroll
        for (int ks = 0; ks < 2; ks++) {
            int k0 = ks * 16 + 2 * tig;
            uint32_t bh[8][2], bl[8][2];
#pragma unroll
            for (int nt = 0; nt < 8; nt++) {
                int nn = wn * 64 + nt * 8 + g;
                bh[nt][0] = *reinterpret_cast<const uint32_t*>(&sBh[nn][k0]);
                bh[nt][1] = *reinterpret_cast<const uint32_t*>(&sBh[nn][k0 + 8]);
                bl[nt][0] = *reinterpret_cast<const uint32_t*>(&sBl[nn][k0]);
                bl[nt][1] = *reinterpret_cast<const uint32_t*>(&sBl[nn][k0 + 8]);
            }
#pragma unroll
            for (int mt = 0; mt < 2; mt++) {
                int r = wm * 32 + mt * 16 + g;
                uint32_t ah[4], al[4];
                ah[0] = *reinterpret_cast<const uint32_t*>(&sAh[r][k0]);
                ah[1] = *reinterpret_cast<const uint32_t*>(&sAh[r + 8][k0]);
                ah[2] = *reinterpret_cast<const uint32_t*>(&sAh[r][k0 + 8]);
                ah[3] = *reinterpret_cast<const uint32_t*>(&sAh[r + 8][k0 + 8]);
                al[0] = *reinterpret_cast<const uint32_t*>(&sAl[r][k0]);
                al[1] = *reinterpret_cast<const uint32_t*>(&sAl[r + 8][k0]);
                al[2] = *reinterpret_cast<const uint32_t*>(&sAl[r][k0 + 8]);
                al[3] = *reinterpret_cast<const uint32_t*>(&sAl[r + 8][k0 + 8]);
#pragma unroll
                for (int nt = 0; nt < 8; nt++) {
                    mma_bf16(acc[mt][nt], ah, bh[nt]);
                    mma_bf16(acc[mt][nt], ah, bl[nt]);
                    mma_bf16(acc[mt][nt], al, bh[nt]);
                }
            }
        }
    }

#pragma unroll
    for (int mt = 0; mt < 2; mt++) {
        int rA = row0 + wm * 32 + mt * 16 + g;
#pragma unroll
        for (int nt = 0; nt < 8; nt++) {
            int cc = bn0 + wn * 64 + nt * 8 + 2 * tig;
            if (rA < n)
                *reinterpret_cast<float2*>(&out[(size_t)rA * NTOT + cc]) =
                    make_float2(acc[mt][nt][0], acc[mt][nt][1]);
            if (rA + 8 < n)
                *reinterpret_cast<float2*>(&out[(size_t)(rA + 8) * NTOT + cc]) =
                    make_float2(acc[mt][nt][2], acc[mt][nt][3]);
        }
    }
}

// ---------------- gather aggregation ----------------
// 16 lanes per node, float4 per lane (64 floats). Layer 1:
// h1 = relu(sum(ar1[src,0:64])/deg + b1 + ar1[node,64:128]) -> g_x2[node,64:128]
__global__ void k_agg1(const float* __restrict__ b1l, int n) {
    int tid = threadIdx.x;
    int node = blockIdx.x * 16 + (tid >> 4);
    int lane = tid & 15;
    if (node >= n) return;
    int deg = min(g_cnti[node], BSTRIDE);
    const int* bk = &g_bucket[node * BSTRIDE];
    float4 a0 = make_float4(0.f, 0.f, 0.f, 0.f);
    float4 a1 = make_float4(0.f, 0.f, 0.f, 0.f);
    int j = 0;
    for (; j + 2 <= deg; j += 2) {
        int s0 = bk[j], s1 = bk[j + 1];
        float4 v0 = *reinterpret_cast<const float4*>(&g_ar1[s0 * 128 + lane * 4]);
        float4 v1 = *reinterpret_cast<const float4*>(&g_ar1[s1 * 128 + lane * 4]);
        a0.x += v0.x; a0.y += v0.y; a0.z += v0.z; a0.w += v0.w;
        a1.x += v1.x; a1.y += v1.y; a1.z += v1.z; a1.w += v1.w;
    }
    if (j < deg) {
        float4 v0 = *reinterpret_cast<const float4*>(&g_ar1[bk[j] * 128 + lane * 4]);
        a0.x += v0.x; a0.y += v0.y; a0.z += v0.z; a0.w += v0.w;
    }
    float inv = 1.0f / fmaxf((float)deg, 1.0f);
    float4 b = *reinterpret_cast<const float4*>(&b1l[lane * 4]);
    float4 r = *reinterpret_cast<const float4*>(&g_ar1[node * 128 + 64 + lane * 4]);
    float4 o;
    o.x = fmaxf((a0.x + a1.x) * inv + b.x + r.x, 0.f);
    o.y = fmaxf((a0.y + a1.y) * inv + b.y + r.y, 0.f);
    o.z = fmaxf((a0.z + a1.z) * inv + b.z + r.z, 0.f);
    o.w = fmaxf((a0.w + a1.w) * inv + b.w + r.w, 0.f);
    *reinterpret_cast<float4*>(&g_x2[node * 128 + 64 + lane * 4]) = o;
}

// Layer 2 aggregation: g_x2[node,0:64] = sum(h1[src])/deg  (h1 = g_x2[:,64:128])
__global__ void k_agg2(int n) {
    int tid = threadIdx.x;
    int node = blockIdx.x * 16 + (tid >> 4);
    int lane = tid & 15;
    if (node >= n) return;
    int deg = min(g_cnti[node], BSTRIDE);
    const int* bk = &g_bucket[node * BSTRIDE];
    float4 a0 = make_float4(0.f, 0.f, 0.f, 0.f);
    float4 a1 = make_float4(0.f, 0.f, 0.f, 0.f);
    int j = 0;
    for (; j + 2 <= deg; j += 2) {
        int s0 = bk[j], s1 = bk[j + 1];
        float4 v0 = *reinterpret_cast<const float4*>(&g_x2[s0 * 128 + 64 + lane * 4]);
        float4 v1 = *reinterpret_cast<const float4*>(&g_x2[s1 * 128 + 64 + lane * 4]);
        a0.x += v0.x; a0.y += v0.y; a0.z += v0.z; a0.w += v0.w;
        a1.x += v1.x; a1.y += v1.y; a1.z += v1.z; a1.w += v1.w;
    }
    if (j < deg) {
        float4 v0 = *reinterpret_cast<const float4*>(&g_x2[bk[j] * 128 + 64 + lane * 4]);
        a0.x += v0.x; a0.y += v0.y; a0.z += v0.z; a0.w += v0.w;
    }
    float inv = 1.0f / fmaxf((float)deg, 1.0f);
    float4 o;
    o.x = (a0.x + a1.x) * inv;
    o.y = (a0.y + a1.y) * inv;
    o.z = (a0.z + a1.z) * inv;
    o.w = (a0.w + a1.w) * inv;
    *reinterpret_cast<float4*>(&g_x2[node * 128 + lane * 4]) = o;
}

// pooling: batch sorted -> block-local register accumulation per column
__global__ void k_pool(const float* __restrict__ b2l,
                       const void* __restrict__ batch, int n) {
    int node0 = blockIdx.x * 64;
    int tid = threadIdx.x;  // column 0..127
    if (node0 >= n) return;
    int is64 = g_is64;
    float bj = b2l[tid];
    float acc = 0.f;
    int curg = load_idx(batch, node0, is64);
    for (int nd = 0; nd < 64; nd++) {
        int node = node0 + nd;
        if (node >= n) break;
        int g = load_idx(batch, node, is64);
        float v = g_h2[node * 128 + tid] + bj;
        if (g != curg) {
            atomicAdd(&g_pool[curg * 128 + tid], acc);
            acc = 0.f;
            curg = g;
        }
        acc += v;
    }
    atomicAdd(&g_pool[curg * 128 + tid], acc);
}

__global__ void k_final(const float* __restrict__ wfc, const float* __restrict__ bfc,
                        float* __restrict__ out) {
    int g = threadIdx.x;
    if (g >= N_GRAPHS) return;
    float inv = 1.0f / fmaxf(g_pool[N_GRAPHS * H2 + g], 1.0f);
    float l[N_CLASSES];
#pragma unroll
    for (int c = 0; c < N_CLASSES; c++) l[c] = bfc[c];
    for (int k = 0; k < H2; k++) {
        float p = g_pool[g * 128 + k] * inv;
#pragma unroll
        for (int c = 0; c < N_CLASSES; c++) l[c] += p * wfc[k * N_CLASSES + c];
    }
    float mx = l[0];
#pragma unroll
    for (int c = 1; c < N_CLASSES; c++) mx = fmaxf(mx, l[c]);
    float s = 0.f;
#pragma unroll
    for (int c = 0; c < N_CLASSES; c++) s += expf(l[c] - mx);
    float lse = mx + logf(s);
#pragma unroll
    for (int c = 0; c < N_CLASSES; c++) out[g * N_CLASSES + c] = l[c] - lse;
}

// ---------------- launch ----------------
extern "C" void kernel_launch(void* const* d_in, const int* in_sizes, int n_in,
                              void* d_out, int out_size) {
    const float* x     = (const float*)d_in[0];
    const void*  ei    = d_in[1];
    const void*  batch = d_in[2];
    const float* w1l   = (const float*)d_in[3];
    const float* b1l   = (const float*)d_in[4];
    const float* w1r   = (const float*)d_in[5];
    const float* w2l   = (const float*)d_in[6];
    const float* b2l   = (const float*)d_in[7];
    const float* w2r   = (const float*)d_in[8];
    const float* wfc   = (const float*)d_in[9];
    const float* bfc   = (const float*)d_in[10];
    float* out = (float*)d_out;

    const int n = N_NODES;

    k_detect<<<1, 1>>>(batch);
    k_zero<<<(N_NODES + 255) / 256, 256>>>();
    k_pack<<<(F_IN * 128 + 128 * 128 + 255) / 256, 256>>>(w1l, w1r, w2l, w2r);
    k_fill<<<(N_EDGES + 255) / 256, 256>>>(ei);
    k_cnt<<<(N_NODES + 255) / 256, 256>>>(batch);

    dim3 grid1((n + 127) / 128, 1);
    k_hmma<512, 128, 0><<<grid1, 256>>>(x, n);
    k_agg1<<<(n + 15) / 16, 256>>>(b1l, n);
    k_agg2<<<(n + 15) / 16, 256>>>(n);
    k_hmma<128, 128, 1><<<grid1, 256>>>(nullptr, n);
    k_pool<<<(n + 63) / 64, 128>>>(b2l, batch, n);

    k_final<<<1, 64>>>(wfc, bfc, out);
}